// round 13
// baseline (speedup 1.0000x reference)
#include <cuda_runtime.h>
#include <cstdint>

// Problem constants
#define Wd 192
#define Hd 192
#define Dd 128
#define Bd 2
#define TX 32
#define TY 8
#define NT 256
#define TILE_W 64                 // cols tx and tx+32 per thread
#define DCHUNK 8                  // z-planes per CTA
#define SROWP 34                  // pairs per row: pc in [0,34) covers cols -1..64
#define PLANEP ((TY + 2) * SROWP) // 340 float2 per z-plane
#define NSLOT 6                   // smem ring depth (4 live + 2 prefetch)

typedef unsigned long long ull;

// ---- packed f32x2 helpers (Blackwell sm_103a) ----
__device__ __forceinline__ ull pack2(float lo, float hi) {
    ull r; asm("mov.b64 %0,{%1,%2};" : "=l"(r) : "f"(lo), "f"(hi)); return r;
}
__device__ __forceinline__ void unpack2(ull v, float& lo, float& hi) {
    asm("mov.b64 {%0,%1},%2;" : "=f"(lo), "=f"(hi) : "l"(v));
}
__device__ __forceinline__ ull fma2(ull a, ull b, ull c) {
    ull d; asm("fma.rn.f32x2 %0,%1,%2,%3;" : "=l"(d) : "l"(a), "l"(b), "l"(c)); return d;
}
__device__ __forceinline__ ull add2(ull a, ull b) {
    ull d; asm("add.rn.f32x2 %0,%1,%2;" : "=l"(d) : "l"(a), "l"(b)); return d;
}
__device__ __forceinline__ float ex2f(float x) {
    float y; asm("ex2.approx.ftz.f32 %0, %1;" : "=f"(y) : "f"(x)); return y;
}
__device__ __forceinline__ void cp4(uint32_t saddr, const float* g) {
    asm volatile("cp.async.ca.shared.global [%0], [%1], 4;"
                 :: "r"(saddr), "l"(g) : "memory");
}

// Range-kernel constant: -log2(e) / (2 * 1.2^2)
#define KRC  (-0.50093579f)
// Degree-3 poly for 2^x on [-0.501, 0] (x-basis; abs err ~5e-6)
#define QC0 0.99999485f
#define QC1 0.69287016f
#define QC2 0.23750570f
#define QC3 0.04665700f

__global__ __launch_bounds__(NT, 5)
void bilat3d_kernel(const float* __restrict__ in, float* __restrict__ out) {
    // Paired layout: smp[slot][r][pc] = (v[r][w0+pc-1], v[r][w0+pc+31])
    __shared__ __align__(16) float2 smp[NSLOT * PLANEP];

    const int tx  = threadIdx.x;
    const int ty  = threadIdx.y;
    const int tid = ty * TX + tx;
    const int w0  = blockIdx.x * TILE_W;
    const int h0  = blockIdx.y * TY;
    const int bz  = blockIdx.z;
    const int b      = bz / (Dd / DCHUNK);
    const int dstart = (bz % (Dd / DCHUNK)) * DCHUNK;

    const float* base = in + (size_t)b * Dd * Hd * Wd;

    uint32_t smb;
    asm("{ .reg .u64 t; cvta.to.shared.u64 t, %1; cvt.u32.u64 %0, t; }"
        : "=r"(smb) : "l"(smp));

    // dd-invariant gather offsets for the paired fill
    auto mkoffs = [&](int i, int& olo, int& ohi) {
        int r  = i / SROWP, pc = i - r * SROWP;
        int gh  = min(max(h0 + r - 1, 0), Hd - 1);
        int glo = min(max(w0 + pc - 1, 0), Wd - 1);
        int ghi = min(w0 + pc + 31, Wd - 1);
        olo = gh * Wd + glo;
        ohi = gh * Wd + ghi;
    };
    const int  i0 = tid, i1 = tid + NT;
    const bool p1 = (i1 < PLANEP);
    int go0lo, go0hi, go1lo = 0, go1hi = 0;
    mkoffs(i0, go0lo, go0hi);
    if (p1) mkoffs(i1, go1lo, go1hi);

    // Async fill of one plane slot
    auto fill = [&](int d, int slot) {
        d = min(max(d, 0), Dd - 1);
        const float* p = base + (size_t)d * Hd * Wd;
        uint32_t a0 = smb + (uint32_t)(slot * PLANEP + i0) * 8u;
        cp4(a0,     p + go0lo);
        cp4(a0 + 4, p + go0hi);
        if (p1) {
            uint32_t a1 = smb + (uint32_t)(slot * PLANEP + i1) * 8u;
            cp4(a1,     p + go1lo);
            cp4(a1 + 4, p + go1hi);
        }
        asm volatile("cp.async.commit_group;" ::: "memory");
    };

    // Prolog: slots 0..3 <- planes dstart-1 .. dstart+2
    fill(dstart - 1, 0);
    fill(dstart,     1);
    fill(dstart + 1, 2);
    fill(dstart + 2, 3);
    asm volatile("cp.async.wait_group 0;" ::: "memory");
    __syncthreads();

    const ull KR2 = pack2(KRC, KRC);
    const ull Q0v = pack2(QC0, QC0);
    const ull Q1v = pack2(QC1, QC1);
    const ull Q2v = pack2(QC2, QC2);
    const ull Q3v = pack2(QC3, QC3);

    const float2* rb = smp + ty * SROWP + tx;   // per-thread pair-row base
    float* outp = out + ((size_t)(b * Dd + dstart) * Hd + (h0 + ty)) * Wd
                      + (w0 + tx);

    // One row-triple applied to one z-output (3 neighbors of that row)
    auto apply = [&](ull qa, ull qb, ull qc, ull B2, ull Cm0,
                     ull& num, ull& den) {
        // dx = 0: polynomial path (fma pipe)
        ull t = fma2(KR2, qb, B2);
        ull u = fma2(t,  qb, Cm0);
        ull p = fma2(Q3v, u, Q2v);
        p = fma2(p, u, Q1v);
        p = fma2(p, u, Q0v);
        num = fma2(p, qb, num);
        den = add2(den, p);
        // dx = -1: MUFU path
        t = fma2(KR2, qa, B2);
        u = fma2(t,  qa, Cm0);
        float uL, uH; unpack2(u, uL, uH);
        ull w = pack2(ex2f(uL), ex2f(uH));
        num = fma2(w, qa, num);
        den = add2(den, w);
        // dx = +1: MUFU path
        t = fma2(KR2, qc, B2);
        u = fma2(t,  qc, Cm0);
        unpack2(u, uL, uH);
        w = pack2(ex2f(uL), ex2f(uH));
        num = fma2(w, qc, num);
        den = add2(den, w);
    };

    // One step = 2 z-outputs (z0, z0+1) sharing the 12 loaded rows.
    // S0..S3 = slots of planes z0-1..z0+2 (compile-time). P0,P1 = prefetch slots.
    auto step = [&](int S0, int S1, int S2, int S3, int P0, int P1,
                    int zc, bool pf) {
        if (pf) { fill(dstart + zc + 3, P0); fill(dstart + zc + 4, P1); }

        // Centers: pair idx tx+1 of middle planes
        const ull cqA = *(const ull*)(rb + S1 * PLANEP + SROWP + 1);
        const ull cqB = *(const ull*)(rb + S2 * PLANEP + SROWP + 1);
        float cAa, cAb, cBa, cBb;
        unpack2(cqA, cAa, cAb);
        unpack2(cqB, cBa, cBb);
        // arg = (KR*n + B)*n + Cm0 = KR*(n-c)^2 ; B = -2*KR*c ; Cm0 = KR*c^2
        const ull B2A = pack2((-2.0f * KRC) * cAa, (-2.0f * KRC) * cAb);
        const ull CmA = pack2(KRC * cAa * cAa, KRC * cAb * cAb);
        const ull B2B = pack2((-2.0f * KRC) * cBa, (-2.0f * KRC) * cBb);
        const ull CmB = pack2(KRC * cBa * cBa, KRC * cBb * cBb);

        ull numA = 0ull, denA = 0ull, numB = 0ull, denB = 0ull;

        #pragma unroll
        for (int zp = 0; zp < 4; ++zp) {
            const int SS = (zp == 0 ? S0 : zp == 1 ? S1 : zp == 2 ? S2 : S3);
            #pragma unroll
            for (int yi = 0; yi < 3; ++yi) {
                const ull* rp = (const ull*)(rb + SS * PLANEP + yi * SROWP);
                const ull qa = rp[0];   // dx=-1 pair
                const ull qb = rp[1];   // dx= 0 pair
                const ull qc = rp[2];   // dx=+1 pair
                if (zp < 3) apply(qa, qb, qc, B2A, CmA, numA, denA);
                if (zp > 0) apply(qa, qb, qc, B2B, CmB, numB, denB);
            }
        }

        float nL, nH, dL, dH;
        float* oA = outp + (size_t)zc * (Hd * Wd);
        unpack2(numA, nL, nH); unpack2(denA, dL, dH);
        oA[0]  = __fdividef(nL, dL);          // den >= ~0.88 always
        oA[32] = __fdividef(nH, dH);
        float* oB = oA + (Hd * Wd);
        unpack2(numB, nL, nH); unpack2(denB, dL, dH);
        oB[0]  = __fdividef(nL, dL);
        oB[32] = __fdividef(nH, dH);

        asm volatile("cp.async.wait_group 0;" ::: "memory");
        __syncthreads();
    };

    // Slot pattern period 3 (plane p -> slot (p+1) mod 6); 4 steps cover z 0..7
    step(0, 1, 2, 3, 4, 5, 0, true);
    step(2, 3, 4, 5, 0, 1, 2, true);
    step(4, 5, 0, 1, 2, 3, 4, true);
    step(0, 1, 2, 3, 4, 5, 6, false);
}

extern "C" void kernel_launch(void* const* d_in, const int* in_sizes, int n_in,
                              void* d_out, int out_size) {
    const float* vol = (const float*)d_in[0];
    float* out = (float*)d_out;
    dim3 grid(Wd / TILE_W, Hd / TY, Bd * (Dd / DCHUNK));  // 3 x 24 x 32 = 2304 CTAs
    dim3 block(TX, TY);                                    // 256 threads
    bilat3d_kernel<<<grid, block>>>(vol, out);
}

// round 15
// speedup vs baseline: 1.6309x; 1.6309x over previous
#include <cuda_runtime.h>
#include <cstdint>

// Problem constants
#define Wd 192
#define Hd 192
#define Dd 128
#define Bd 2
#define TX 32
#define TY 8
#define NT 256
#define TILE_W 64                 // cols tx and tx+32 per thread
#define DCHUNK 16                 // z-planes per CTA
#define SROWP 34                  // pairs per row: pc in [0,34) covers cols -1..64
#define PLANEP ((TY + 2) * SROWP) // 340 float2 per z-plane
#define NSLOT 8                   // ring: 4-plane window + 2x2-plane prefetch

typedef unsigned long long ull;

// ---- packed f32x2 helpers (Blackwell sm_103a) ----
__device__ __forceinline__ ull pack2(float lo, float hi) {
    ull r; asm("mov.b64 %0,{%1,%2};" : "=l"(r) : "f"(lo), "f"(hi)); return r;
}
__device__ __forceinline__ void unpack2(ull v, float& lo, float& hi) {
    asm("mov.b64 {%0,%1},%2;" : "=f"(lo), "=f"(hi) : "l"(v));
}
__device__ __forceinline__ ull fma2(ull a, ull b, ull c) {
    ull d; asm("fma.rn.f32x2 %0,%1,%2,%3;" : "=l"(d) : "l"(a), "l"(b), "l"(c)); return d;
}
__device__ __forceinline__ ull add2(ull a, ull b) {
    ull d; asm("add.rn.f32x2 %0,%1,%2;" : "=l"(d) : "l"(a), "l"(b)); return d;
}
__device__ __forceinline__ float ex2f(float x) {
    float y; asm("ex2.approx.ftz.f32 %0, %1;" : "=f"(y) : "f"(x)); return y;
}
__device__ __forceinline__ void cp4(uint32_t saddr, const float* g) {
    asm volatile("cp.async.ca.shared.global [%0], [%1], 4;"
                 :: "r"(saddr), "l"(g) : "memory");
}
__device__ __forceinline__ void commitg() {
    asm volatile("cp.async.commit_group;" ::: "memory");
}
__device__ __forceinline__ void waitg0() {
    asm volatile("cp.async.wait_group 0;" ::: "memory");
}
__device__ __forceinline__ void waitg1() {
    asm volatile("cp.async.wait_group 1;" ::: "memory");
}

// Range-kernel constant: -log2(e) / (2 * 1.2^2)
#define KRC  (-0.50093579f)
// Degree-3 poly for 2^x on [-0.501, 0] (x-basis; abs err ~5e-6)
#define QC0 0.99999485f
#define QC1 0.69287016f
#define QC2 0.23750570f
#define QC3 0.04665700f

__global__ __launch_bounds__(NT, 4)
void bilat3d_kernel(const float* __restrict__ in, float* __restrict__ out) {
    // Paired layout: smp[slot][r][pc] = (v[r][w0+pc-1], v[r][w0+pc+31])
    __shared__ __align__(16) float2 smp[NSLOT * PLANEP];

    const int tx  = threadIdx.x;
    const int ty  = threadIdx.y;
    const int tid = ty * TX + tx;
    const int w0  = blockIdx.x * TILE_W;
    const int h0  = blockIdx.y * TY;
    const int bz  = blockIdx.z;
    const int b      = bz / (Dd / DCHUNK);
    const int dstart = (bz % (Dd / DCHUNK)) * DCHUNK;

    const float* base = in + (size_t)b * Dd * Hd * Wd;

    uint32_t smb;
    asm("{ .reg .u64 t; cvta.to.shared.u64 t, %1; cvt.u32.u64 %0, t; }"
        : "=r"(smb) : "l"(smp));

    // dd-invariant gather offsets for the paired fill
    auto mkoffs = [&](int i, int& olo, int& ohi) {
        int r  = i / SROWP, pc = i - r * SROWP;
        int gh  = min(max(h0 + r - 1, 0), Hd - 1);
        int glo = min(max(w0 + pc - 1, 0), Wd - 1);
        int ghi = min(w0 + pc + 31, Wd - 1);
        olo = gh * Wd + glo;
        ohi = gh * Wd + ghi;
    };
    const int  i0 = tid, i1 = tid + NT;
    const bool p1 = (i1 < PLANEP);
    int go0lo, go0hi, go1lo = 0, go1hi = 0;
    mkoffs(i0, go0lo, go0hi);
    if (p1) mkoffs(i1, go1lo, go1hi);

    // Async fill of one plane slot (no commit; caller groups fills)
    auto fillnc = [&](int d, int slot) {
        d = min(max(d, 0), Dd - 1);
        const float* p = base + (size_t)d * Hd * Wd;
        uint32_t a0 = smb + (uint32_t)(slot * PLANEP + i0) * 8u;
        cp4(a0,     p + go0lo);
        cp4(a0 + 4, p + go0hi);
        if (p1) {
            uint32_t a1 = smb + (uint32_t)(slot * PLANEP + i1) * 8u;
            cp4(a1,     p + go1lo);
            cp4(a1 + 4, p + go1hi);
        }
    };

    // Prolog: slots 0..5 <- planes dstart-1 .. dstart+4 (windows of steps 0,1)
    #pragma unroll
    for (int s = 0; s < 6; ++s) fillnc(dstart - 1 + s, s);
    commitg();
    waitg0();
    __syncthreads();

    const ull KR2 = pack2(KRC, KRC);
    const ull Q0v = pack2(QC0, QC0);
    const ull Q1v = pack2(QC1, QC1);
    const ull Q2v = pack2(QC2, QC2);
    const ull Q3v = pack2(QC3, QC3);

    const float2* rb = smp + ty * SROWP + tx;   // per-thread pair-row base
    float* outp = out + ((size_t)(b * Dd + dstart) * Hd + (h0 + ty)) * Wd
                      + (w0 + tx);

    // One row-triple applied to one z-output (3 neighbors of that row)
    auto apply = [&](ull qa, ull qb, ull qc, ull B2, ull Cm0,
                     ull& num, ull& den) {
        // dx = 0: polynomial path (fma pipe)
        ull t = fma2(KR2, qb, B2);
        ull u = fma2(t,  qb, Cm0);
        ull p = fma2(Q3v, u, Q2v);
        p = fma2(p, u, Q1v);
        p = fma2(p, u, Q0v);
        num = fma2(p, qb, num);
        den = add2(den, p);
        // dx = -1: MUFU path
        t = fma2(KR2, qa, B2);
        u = fma2(t,  qa, Cm0);
        float uL, uH; unpack2(u, uL, uH);
        ull w = pack2(ex2f(uL), ex2f(uH));
        num = fma2(w, qa, num);
        den = add2(den, w);
        // dx = +1: MUFU path
        t = fma2(KR2, qc, B2);
        u = fma2(t,  qc, Cm0);
        unpack2(u, uL, uH);
        w = pack2(ex2f(uL), ex2f(uH));
        num = fma2(w, qc, num);
        den = add2(den, w);
    };

    // One step = 2 z-outputs (zc, zc+1). Window slots W0..W3 hold planes
    // zc-1..zc+2; fills go 2 steps ahead (planes zc+5, zc+6 -> F0, F1).
    // waitmode: 1 -> wait_group 1 (1 group may stay in flight), 0 -> drain,
    // -1 -> none (last step; everything already drained).
    auto step = [&](int W0, int W1, int W2, int W3, int F0, int F1,
                    int zc, bool pf, int waitmode) {
        if (pf) {
            fillnc(dstart + zc + 5, F0);
            fillnc(dstart + zc + 6, F1);
            commitg();
        }

        // Centers: pair idx tx+1 of middle planes
        const ull cqA = *(const ull*)(rb + W1 * PLANEP + SROWP + 1);
        const ull cqB = *(const ull*)(rb + W2 * PLANEP + SROWP + 1);
        float cAa, cAb, cBa, cBb;
        unpack2(cqA, cAa, cAb);
        unpack2(cqB, cBa, cBb);
        // arg = (KR*n + B)*n + Cm0 = KR*(n-c)^2 ; B = -2*KR*c ; Cm0 = KR*c^2
        const ull B2A = pack2((-2.0f * KRC) * cAa, (-2.0f * KRC) * cAb);
        const ull CmA = pack2(KRC * cAa * cAa, KRC * cAb * cAb);
        const ull B2B = pack2((-2.0f * KRC) * cBa, (-2.0f * KRC) * cBb);
        const ull CmB = pack2(KRC * cBa * cBa, KRC * cBb * cBb);

        ull numA = 0ull, denA = 0ull, numB = 0ull, denB = 0ull;

        #pragma unroll
        for (int zp = 0; zp < 4; ++zp) {
            const int SS = (zp == 0 ? W0 : zp == 1 ? W1 : zp == 2 ? W2 : W3);
            #pragma unroll
            for (int yi = 0; yi < 3; ++yi) {
                const ull* rp = (const ull*)(rb + SS * PLANEP + yi * SROWP);
                const ull qa = rp[0];   // dx=-1 pair
                const ull qb = rp[1];   // dx= 0 pair
                const ull qc = rp[2];   // dx=+1 pair
                if (zp < 3) apply(qa, qb, qc, B2A, CmA, numA, denA);
                if (zp > 0) apply(qa, qb, qc, B2B, CmB, numB, denB);
            }
        }

        float nL, nH, dL, dH;
        float* oA = outp + (size_t)zc * (Hd * Wd);
        unpack2(numA, nL, nH); unpack2(denA, dL, dH);
        oA[0]  = __fdividef(nL, dL);          // den >= ~0.88 always
        oA[32] = __fdividef(nH, dH);
        float* oB = oA + (Hd * Wd);
        unpack2(numB, nL, nH); unpack2(denB, dL, dH);
        oB[0]  = __fdividef(nL, dL);
        oB[32] = __fdividef(nH, dH);

        if (waitmode == 1)      waitg1();
        else if (waitmode == 0) waitg0();
        __syncthreads();
    };

    // Slot schedule: plane (z - dstart + 1) -> slot mod 8; window stride 2
    // -> period-4 compile-time pattern. Fills at step k are first read at
    // step k+2 (wait_group 1 gives them ~2 compute phases to land).
    step(0, 1, 2, 3, 6, 7,  0, true,  1);
    step(2, 3, 4, 5, 0, 1,  2, true,  1);
    step(4, 5, 6, 7, 2, 3,  4, true,  1);
    step(6, 7, 0, 1, 4, 5,  6, true,  1);
    step(0, 1, 2, 3, 6, 7,  8, true,  1);
    step(2, 3, 4, 5, 0, 1, 10, true,  1);
    step(4, 5, 6, 7, 2, 3, 12, false, 0);   // drain: step 7 reads last fills
    step(6, 7, 0, 1, 4, 5, 14, false, -1);
}

extern "C" void kernel_launch(void* const* d_in, const int* in_sizes, int n_in,
                              void* d_out, int out_size) {
    const float* vol = (const float*)d_in[0];
    float* out = (float*)d_out;
    dim3 grid(Wd / TILE_W, Hd / TY, Bd * (Dd / DCHUNK));  // 3 x 24 x 16 = 1152 CTAs
    dim3 block(TX, TY);                                    // 256 threads
    bilat3d_kernel<<<grid, block>>>(vol, out);
}